// round 11
// baseline (speedup 1.0000x reference)
#include <cuda_runtime.h>
#include <cuda_bf16.h>
#include <mma.h>
#include <math.h>
#include <stdint.h>

using namespace nvcuda;

#define TT   500
#define BB   8
#define CC   512
#define RR   4000
#define TBC  2048000
#define LANES 4096

// ---------------- scratch ----------------
__device__ float d_pre[3 * TBC];
__device__ float d_spk[3 * TBC];
__device__ float d_pre2[3 * TBC];
__device__ float d_spk2[3 * TBC];
__device__ float d_dwout[TBC];
__device__ float d_M[64 * 64 * 64];
__device__ float d_meanb[1536];
__device__ float d_rstdb[1536];
__device__ float d_bnpart[3 * 25 * 1024];
__device__ __nv_bfloat16 d_Aq[(size_t)4000 * 3072];
__device__ __nv_bfloat16 d_Bq[(size_t)1536 * 3072];
__device__ __nv_bfloat16 d_As[(size_t)4000 * 1536];
__device__ __nv_bfloat16 d_Bs0[(size_t)512 * 1536];
__device__ __nv_bfloat16 d_Bs1[(size_t)512 * 1536];
__device__ uint32_t d_qbD[65536];                 // q bits along d (per t,b,h,half)
__device__ uint32_t d_kbD[65536];                 // k bits along d
__device__ unsigned long long d_kbT[32768];       // k bits along t (per bh,d)
__device__ unsigned long long d_vbT[32768];       // v bits along t

static __device__ __forceinline__ uint32_t smem_u32(const void* p) {
    return (uint32_t)__cvta_generic_to_shared(p);
}

// ---------------- bf16 3-way split ----------------
static __device__ __forceinline__ void split3(float x, __nv_bfloat16& a,
                                              __nv_bfloat16& b, __nv_bfloat16& c) {
    a = __float2bfloat16(x);
    float r = x - __bfloat162float(a);
    b = __float2bfloat16(r);
    r = r - __bfloat162float(b);
    c = __float2bfloat16(r);
}

// A' segs = [x1, x1, x2, x1, x2, x3]
__global__ void split_x_k(const float* __restrict__ x, __nv_bfloat16* __restrict__ A)
{
    int i = blockIdx.x * 256 + threadIdx.x;
    if (i >= TBC) return;
    __nv_bfloat16 a, b, c;
    split3(x[i], a, b, c);
    size_t base = (size_t)(i >> 9) * 3072 + (i & 511);
    A[base] = a; A[base + 512] = a; A[base + 1024] = b;
    A[base + 1536] = a; A[base + 2048] = b; A[base + 2560] = c;
}

// B' segs = [w1, w2, w1, w3, w2, w1]
__global__ void split_wqkv_k(const float* __restrict__ wq, const float* __restrict__ wk,
                             const float* __restrict__ wv, __nv_bfloat16* __restrict__ B)
{
    int i = blockIdx.x * 256 + threadIdx.x;
    if (i >= 1536 * 512) return;
    int n = i >> 9, k = i & 511;
    const float* w = (n < 512) ? wq : (n < 1024) ? wk : wv;
    __nv_bfloat16 a, b, c;
    split3(w[(size_t)(n & 511) * 512 + k], a, b, c);
    size_t base = (size_t)n * 3072 + k;
    B[base] = a; B[base + 512] = b; B[base + 1024] = a;
    B[base + 1536] = c; B[base + 2048] = b; B[base + 2560] = a;
}

// B'' segs = [w1, w2, w3]
__global__ void split_ws_k(const float* __restrict__ w, __nv_bfloat16* __restrict__ B)
{
    int i = blockIdx.x * 256 + threadIdx.x;
    if (i >= 512 * 512) return;
    int n = i >> 9, k = i & 511;
    __nv_bfloat16 a, b, c;
    split3(w[(size_t)n * 512 + k], a, b, c);
    size_t base = (size_t)n * 1536 + k;
    B[base] = a; B[base + 512] = b; B[base + 1024] = c;
}

// ---------------- cp.async helper ----------------
static __device__ __forceinline__ void cpa16(uint32_t dst, const void* src, bool ok)
{
    int sz = ok ? 16 : 0;
    asm volatile("cp.async.cg.shared.global [%0], [%1], 16, %2;"
                 :: "r"(dst), "l"(src), "r"(sz));
}

// ---------------- wmma bf16 GEMM (HMMA path), single-sync 2-stage pipeline ----
#define LDT 40
#define ABYTES 10240
__global__ __launch_bounds__(256)
void wmma_gemm(const __nv_bfloat16* __restrict__ A, const __nv_bfloat16* __restrict__ B,
               float* __restrict__ outp, int Mrows, int Ktot, size_t segStride)
{
    __shared__ __align__(16) __nv_bfloat16 sm[20480];
    int tid = threadIdx.x, wid = tid >> 5, lane = tid & 31;
    int wr = wid >> 1, wc = wid & 1;
    uint32_t sa = smem_u32(sm);
    int bm = blockIdx.y * 128, bn = blockIdx.x * 128;
    const __nv_bfloat16* Ab = A + (size_t)bm * Ktot;
    const __nv_bfloat16* Bb = B + (size_t)bn * Ktot;
    int amax = Mrows - bm; if (amax > 128) amax = 128;

    int ch0 = tid, ch1 = tid + 256;
    int r0 = ch0 >> 2, c0 = (ch0 & 3) * 8;
    int r1 = ch1 >> 2, c1 = (ch1 & 3) * 8;
    int r0c = (r0 < amax) ? r0 : (amax - 1);
    int r1c = (r1 < amax) ? r1 : (amax - 1);

    int nk = Ktot >> 5;

    // prologue: stage 0
    cpa16(sa + (uint32_t)(r0 * LDT + c0) * 2, Ab + (size_t)r0c * Ktot + c0, r0 < amax);
    cpa16(sa + (uint32_t)(r1 * LDT + c1) * 2, Ab + (size_t)r1c * Ktot + c1, r1 < amax);
    cpa16(sa + 2 * ABYTES + (uint32_t)(r0 * LDT + c0) * 2, Bb + (size_t)r0 * Ktot + c0, true);
    cpa16(sa + 2 * ABYTES + (uint32_t)(r1 * LDT + c1) * 2, Bb + (size_t)r1 * Ktot + c1, true);
    asm volatile("cp.async.commit_group;");

    wmma::fragment<wmma::accumulator, 16, 16, 16, float> acc[2][4];
#pragma unroll
    for (int i = 0; i < 2; i++)
#pragma unroll
        for (int j = 0; j < 4; j++) wmma::fill_fragment(acc[i][j], 0.0f);

    for (int k0 = 0; k0 < nk; k0++) {
        asm volatile("cp.async.wait_group 0;");
        __syncthreads();
        if (k0 + 1 < nk) {
            int nb = (k0 + 1) & 1;
            int kof = (k0 + 1) * 32;
            uint32_t abo = sa + (uint32_t)nb * ABYTES;
            uint32_t bbo = sa + 2 * ABYTES + (uint32_t)nb * ABYTES;
            cpa16(abo + (uint32_t)(r0 * LDT + c0) * 2, Ab + (size_t)r0c * Ktot + kof + c0, r0 < amax);
            cpa16(abo + (uint32_t)(r1 * LDT + c1) * 2, Ab + (size_t)r1c * Ktot + kof + c1, r1 < amax);
            cpa16(bbo + (uint32_t)(r0 * LDT + c0) * 2, Bb + (size_t)r0 * Ktot + kof + c0, true);
            cpa16(bbo + (uint32_t)(r1 * LDT + c1) * 2, Bb + (size_t)r1 * Ktot + kof + c1, true);
            asm volatile("cp.async.commit_group;");
        }
        int buf = k0 & 1;
        const __nv_bfloat16* As_ = sm + buf * (ABYTES / 2);
        const __nv_bfloat16* Bs_ = sm + ABYTES + buf * (ABYTES / 2);
#pragma unroll
        for (int kk = 0; kk < 2; kk++) {
            wmma::fragment<wmma::matrix_a, 16, 16, 16, __nv_bfloat16, wmma::row_major> af[2];
            wmma::fragment<wmma::matrix_b, 16, 16, 16, __nv_bfloat16, wmma::col_major> bf[4];
#pragma unroll
            for (int i = 0; i < 2; i++)
                wmma::load_matrix_sync(af[i], As_ + (wr * 32 + i * 16) * LDT + kk * 16, LDT);
#pragma unroll
            for (int j = 0; j < 4; j++)
                wmma::load_matrix_sync(bf[j], Bs_ + (wc * 64 + j * 16) * LDT + kk * 16, LDT);
#pragma unroll
            for (int i = 0; i < 2; i++)
#pragma unroll
                for (int j = 0; j < 4; j++)
                    wmma::mma_sync(acc[i][j], af[i], bf[j], acc[i][j]);
        }
    }

    float* outbase = outp + (size_t)(bn >> 9) * segStride + (bn & 511);
    if (amax == 128) {
#pragma unroll
        for (int i = 0; i < 2; i++)
#pragma unroll
            for (int j = 0; j < 4; j++) {
                int m = bm + wr * 32 + i * 16;
                int n = wc * 64 + j * 16;
                wmma::store_matrix_sync(outbase + (size_t)m * 512 + n, acc[i][j], 512,
                                        wmma::mem_row_major);
            }
    } else {
        __syncthreads();
        float* scr = (float*)sm + wid * 256;
#pragma unroll
        for (int i = 0; i < 2; i++)
#pragma unroll
            for (int j = 0; j < 4; j++) {
                wmma::store_matrix_sync(scr, acc[i][j], 16, wmma::mem_row_major);
                __syncwarp();
#pragma unroll
                for (int q = 0; q < 8; q++) {
                    int e = lane * 8 + q;
                    int r = e >> 4, cc2 = e & 15;
                    int m = bm + wr * 32 + i * 16 + r;
                    if (m < Mrows)
                        outbase[(size_t)m * 512 + wc * 64 + j * 16 + cc2] = scr[e];
                }
                __syncwarp();
            }
    }
}

// ---------------- BN stats: deterministic 2-stage ----------------
__global__ void bn_part(const float* __restrict__ pre, float* __restrict__ part)
{
    int z = blockIdx.z;
    int cl = threadIdx.x & 31;
    int c = blockIdx.x * 32 + cl;
    int rg = threadIdx.x >> 5;
    const float* p = pre + (size_t)z * TBC;
    int r0 = blockIdx.y * 160;
    float s = 0.f, s2 = 0.f;
#pragma unroll 5
    for (int r = r0 + rg; r < r0 + 160; r += 8) {
        float v = p[(size_t)r * CC + c];
        s += v; s2 = fmaf(v, v, s2);
    }
    __shared__ float sh1[8][32], sh2[8][32];
    sh1[rg][cl] = s; sh2[rg][cl] = s2;
    __syncthreads();
    if (rg == 0) {
#pragma unroll
        for (int i = 1; i < 8; i++) { s += sh1[i][cl]; s2 += sh2[i][cl]; }
        size_t b = ((size_t)z * 25 + blockIdx.y) * 1024;
        part[b + c] = s;
        part[b + 512 + c] = s2;
    }
}

__global__ void bn_fin(const float* __restrict__ part, float* __restrict__ mean,
                       float* __restrict__ rstd)
{
    int z = blockIdx.x, c = threadIdx.x;
    float s = 0.f, s2 = 0.f;
#pragma unroll 5
    for (int i = 0; i < 25; i++) {
        size_t b = ((size_t)z * 25 + i) * 1024;
        s += part[b + c];
        s2 += part[b + 512 + c];
    }
    float m = s * (1.f / RR);
    float var = s2 * (1.f / RR) - m * m;
    mean[z * 512 + c] = m;
    rstd[z * 512 + c] = 1.f / sqrtf(var + 1e-5f);
}

// ---------------- LIF scan ----------------
// MODE 0: plain  MODE 1: BN affine  MODE 2: x = pre + a1 + a2
// WA: emit bf16 triple [s,s,s] into abuf.  PACK: emit spike bitpacks (QKV pass):
//   m==0 (q): ballot words along d   m==1 (k): ballot words + along-t words (skip float)
//   m==2 (v): along-t words
template <int MODE, int WA, int PACK>
__global__ void lif_k(const float* __restrict__ pre,
                      const float* __restrict__ a1, const float* __restrict__ a2,
                      const float* __restrict__ mean, const float* __restrict__ rstd,
                      const float* __restrict__ gamma, const float* __restrict__ beta,
                      float* __restrict__ out, __nv_bfloat16* __restrict__ abuf,
                      uint32_t* __restrict__ qbD, uint32_t* __restrict__ kbD,
                      unsigned long long* __restrict__ kbT,
                      unsigned long long* __restrict__ vbT, int nlanes)
{
    int lane = blockIdx.x * blockDim.x + threadIdx.x;
    if (lane >= nlanes) return;
    int m   = lane >> 12;
    int l12 = lane & 4095;
    const float* p = pre + (size_t)m * TBC + l12;
    float* o = out + (size_t)m * TBC + l12;
    float mn = 0.f, rs = 1.f, ga = 1.f, be = 0.f;
    if (MODE == 1) {
        int c = (m << 9) | (l12 & 511);
        mn = mean[c]; rs = rstd[c]; ga = gamma[c]; be = beta[c];
    }
    int bidx = l12 >> 9, cch = l12 & 511;
    int hh = cch >> 6, half = (cch >> 5) & 1, dd = cch & 63;
    int bh = bidx * 8 + hh;
    unsigned long long cur = 0;
    float v = 0.f;
#pragma unroll 25
    for (int t = 0; t < TT; t++) {
        float x = p[(size_t)t * LANES];
        if (MODE == 2) x = x + a1[l12 + (size_t)t * LANES] + a2[l12 + (size_t)t * LANES];
        if (MODE == 1) x = ((x - mn) * rs) * ga + be;
        float h = fmaf(v, 0.5f, x);
        bool sp = (h - 1.0f) >= 0.0f;
        if (!(PACK && m == 1)) o[(size_t)t * LANES] = sp ? 1.0f : 0.0f;
        if (WA) {
            __nv_bfloat16 sv = __float2bfloat16(sp ? 1.0f : 0.0f);
            size_t ab = ((size_t)(t * BB + bidx)) * 1536 + cch;
            abuf[ab] = sv; abuf[ab + 512] = sv; abuf[ab + 1024] = sv;
        }
        if (PACK) {
            unsigned bal = __ballot_sync(0xffffffffu, sp);
            if (m == 0) {
                if ((threadIdx.x & 31) == 0) qbD[((t * 8 + bidx) * 8 + hh) * 2 + half] = bal;
            } else if (m == 1) {
                if ((threadIdx.x & 31) == 0) kbD[((t * 8 + bidx) * 8 + hh) * 2 + half] = bal;
                cur |= (unsigned long long)(sp ? 1u : 0u) << (t & 63);
                if ((t & 63) == 63) { kbT[(bh * 64 + dd) * 8 + (t >> 6)] = cur; cur = 0; }
            } else {
                cur |= (unsigned long long)(sp ? 1u : 0u) << (t & 63);
                if ((t & 63) == 63) { vbT[(bh * 64 + dd) * 8 + (t >> 6)] = cur; cur = 0; }
            }
        }
        v = sp ? 0.0f : h;
    }
    if (PACK) {
        if (m == 1) kbT[(bh * 64 + dd) * 8 + 7] = cur;
        else if (m == 2) vbT[(bh * 64 + dd) * 8 + 7] = cur;
    }
}

// ---------------- K^T V via popcount over t-packed bits ----------------
__global__ void kv_pop(const unsigned long long* __restrict__ kbT,
                       const unsigned long long* __restrict__ vbT,
                       float* __restrict__ M)
{
    __shared__ unsigned long long kb[64][8], vb[64][8];
    int bh = blockIdx.x, tid = threadIdx.x;
    for (int i = tid; i < 512; i += 256) {
        kb[i >> 3][i & 7] = kbT[bh * 512 + i];
        vb[i >> 3][i & 7] = vbT[bh * 512 + i];
    }
    __syncthreads();
#pragma unroll
    for (int q = 0; q < 16; q++) {
        int e = tid * 16 + q;
        int d1 = e >> 6, d2 = e & 63;
        int acc = 0;
#pragma unroll
        for (int w = 0; w < 8; w++) acc += __popcll(kb[d1][w] & vb[d2][w]);
        M[bh * 4096 + e] = (float)acc;
    }
}

// ---------------- global branch: g_pre = (Q M) * gscale ----------------
__global__ void qM_k(const float* __restrict__ qspk, const float* __restrict__ M,
                     float* __restrict__ gpre, float gscale)
{
    int bh = blockIdx.x; int b = bh >> 3, h = bh & 7;
    __shared__ float Ms[64][65];
    for (int i = threadIdx.x; i < 4096; i += 256) Ms[i >> 6][i & 63] = M[bh * 4096 + i];
    __syncthreads();
    int warp = threadIdx.x >> 5, lane = threadIdx.x & 31;
    int tstart = blockIdx.y * 100;
    for (int t = tstart + warp; t < tstart + 100; t += 8) {
        size_t base = (size_t)(t * BB + b) * CC + h * 64;
        float q0 = qspk[base + lane], q1 = qspk[base + 32 + lane];
        float a0 = 0.f, a1v = 0.f;
#pragma unroll
        for (int d1 = 0; d1 < 32; d1++) {
            float qv = __shfl_sync(0xffffffffu, q0, d1);
            a0 = fmaf(qv, Ms[d1][lane], a0);
            a1v = fmaf(qv, Ms[d1][lane + 32], a1v);
        }
#pragma unroll
        for (int d1 = 0; d1 < 32; d1++) {
            float qv = __shfl_sync(0xffffffffu, q1, d1);
            a0 = fmaf(qv, Ms[d1 + 32][lane], a0);
            a1v = fmaf(qv, Ms[d1 + 32][lane + 32], a1v);
        }
        gpre[base + lane] = a0 * gscale;
        gpre[base + 32 + lane] = a1v * gscale;
    }
}

// ---------------- local banded attention (bitmask loads from LIF packs) --------
__global__ void local_k(const uint32_t* __restrict__ qbD, const uint32_t* __restrict__ kbD,
                        const float* __restrict__ vspk, float* __restrict__ lpre, float lscale)
{
    int bh = blockIdx.x; int b = bh >> 3, h = bh & 7;
    int t0 = blockIdx.y * 64;
    __shared__ unsigned long long qb[64], kb[104];
    __shared__ float vsm[104][64];
    __shared__ float ss[64][41];
    int tid = threadIdx.x;
    for (int i = tid; i < 64; i += 256) {
        int t = t0 + i;
        unsigned long long w = 0;
        if (t < TT) {
            int ix = ((t * 8 + b) * 8 + h) * 2;
            w = (unsigned long long)qbD[ix] | ((unsigned long long)qbD[ix + 1] << 32);
        }
        qb[i] = w;
    }
    for (int i = tid; i < 104; i += 256) {
        int t = t0 + i - 20;
        unsigned long long w = 0;
        if (t >= 0 && t < TT) {
            int ix = ((t * 8 + b) * 8 + h) * 2;
            w = (unsigned long long)kbD[ix] | ((unsigned long long)kbD[ix + 1] << 32);
        }
        kb[i] = w;
    }
    for (int i = tid; i < 104 * 64; i += 256) {
        int r = i >> 6, dd = i & 63;
        int t = t0 + r - 20;
        vsm[r][dd] = (t >= 0 && t < TT)
                   ? vspk[(size_t)(t * BB + b) * CC + h * 64 + dd] : 0.f;
    }
    __syncthreads();
    for (int i = tid; i < 64 * 41; i += 256) {
        int tt = i / 41, o = i % 41;
        ss[tt][o] = (float)__popcll(qb[tt] & kb[tt + o]);
    }
    __syncthreads();
    int d = tid & 63, tg = tid >> 6;
    for (int tt = tg; tt < 64; tt += 4) {
        int t = t0 + tt;
        if (t >= TT) continue;
        float acc = 0.f;
#pragma unroll
        for (int o = 0; o < 41; o++) acc = fmaf(ss[tt][o], vsm[tt + o][d], acc);
        lpre[(size_t)(t * BB + b) * CC + h * 64 + d] = acc * lscale;
    }
}

// ---------------- depthwise temporal conv ----------------
__global__ void dwconv_k(const float* __restrict__ vspk, const float* __restrict__ wdw,
                         float* __restrict__ out)
{
    int i = blockIdx.x * 256 + threadIdx.x;
    if (i >= TBC) return;
    int t = i >> 12; int bc = i & 4095; int c = bc & 511; int h = c >> 6;
    float acc = 0.f;
#pragma unroll
    for (int j = 0; j < 9; j++) {
        int tt = t + j - 4;
        if (tt >= 0 && tt < TT) acc = fmaf(vspk[(size_t)tt * LANES + bc], wdw[h * 9 + j], acc);
    }
    out[i] = acc;
}

// ---------------- pointwise over heads ----------------
__global__ void pw_k(const float* __restrict__ dwspk, const float* __restrict__ wpw,
                     float* __restrict__ out)
{
    int i = blockIdx.x * 256 + threadIdx.x;
    if (i >= 256000) return;
    int t = i / 512; int bd = i % 512; int b = bd >> 6; int d = bd & 63;
    size_t base = (size_t)t * LANES + b * 512 + d;
    float s[8];
#pragma unroll
    for (int h2 = 0; h2 < 8; h2++) s[h2] = dwspk[base + h2 * 64];
#pragma unroll
    for (int g = 0; g < 8; g++) {
        float acc = 0.f;
#pragma unroll
        for (int h2 = 0; h2 < 8; h2++) acc = fmaf(s[h2], wpw[g * 8 + h2], acc);
        out[base + g * 64] = acc;
    }
}

// ---------------- host launch ----------------
extern "C" void kernel_launch(void* const* d_in, const int* in_sizes, int n_in,
                              void* d_out, int out_size)
{
    const float* x      = (const float*)d_in[0];
    const float* wq     = (const float*)d_in[1];
    const float* wk     = (const float*)d_in[2];
    const float* wv     = (const float*)d_in[3];
    const float* wmattn = (const float*)d_in[4];
    const float* wproj  = (const float*)d_in[5];
    const float* wdw    = (const float*)d_in[6];
    const float* wpw    = (const float*)d_in[7];
    const float* gamma  = (const float*)d_in[8];
    const float* beta   = (const float*)d_in[9];
    float* out = (float*)d_out;

    float *pre, *spk, *pre2, *spk2, *dwout, *M, *meanb, *rstdb, *bnpart;
    __nv_bfloat16 *Aq, *Bq, *As, *Bs0, *Bs1;
    uint32_t *qbD, *kbD;
    unsigned long long *kbT, *vbT;
    cudaGetSymbolAddress((void**)&pre,    d_pre);
    cudaGetSymbolAddress((void**)&spk,    d_spk);
    cudaGetSymbolAddress((void**)&pre2,   d_pre2);
    cudaGetSymbolAddress((void**)&spk2,   d_spk2);
    cudaGetSymbolAddress((void**)&dwout,  d_dwout);
    cudaGetSymbolAddress((void**)&M,      d_M);
    cudaGetSymbolAddress((void**)&meanb,  d_meanb);
    cudaGetSymbolAddress((void**)&rstdb,  d_rstdb);
    cudaGetSymbolAddress((void**)&bnpart, d_bnpart);
    cudaGetSymbolAddress((void**)&Aq,  d_Aq);
    cudaGetSymbolAddress((void**)&Bq,  d_Bq);
    cudaGetSymbolAddress((void**)&As,  d_As);
    cudaGetSymbolAddress((void**)&Bs0, d_Bs0);
    cudaGetSymbolAddress((void**)&Bs1, d_Bs1);
    cudaGetSymbolAddress((void**)&qbD, d_qbD);
    cudaGetSymbolAddress((void**)&kbD, d_kbD);
    cudaGetSymbolAddress((void**)&kbT, d_kbT);
    cudaGetSymbolAddress((void**)&vbT, d_vbT);

    float lscale = (float)(1.0 / (double)(float)sqrt(2624.0));
    float gscale = (float)(1.0 / (double)(float)sqrt(32000.0));

    // operand prep
    split_x_k<<<8000, 256>>>(x, Aq);
    split_wqkv_k<<<3072, 256>>>(wq, wk, wv, Bq);
    split_ws_k<<<1024, 256>>>(wmattn, Bs0);
    split_ws_k<<<1024, 256>>>(wproj, Bs1);

    // QKV: one wmma GEMM, N=1536 -> q,k,v pre-activations
    wmma_gemm<<<dim3(12, 32), 256>>>(Aq, Bq, pre, RR, 3072, (size_t)TBC);
    bn_part<<<dim3(16, 25, 3), 256>>>(pre, bnpart);
    bn_fin<<<3, 512>>>(bnpart, meanb, rstdb);
    // LIF + inline spike bit-packing (q: d-ballots, k: d-ballots + t-words, v: t-words)
    lif_k<1, 0, 1><<<96, 128>>>(pre, nullptr, nullptr, meanb, rstdb, gamma, beta,
                                spk, nullptr, qbD, kbD, kbT, vbT, 3 * LANES);

    // global linear attention: M = K^T V (popcount), then Q M
    kv_pop<<<64, 256>>>(kbT, vbT, M);
    qM_k<<<dim3(64, 5), 256>>>(spk, M, pre2, gscale);

    // local banded attention (bitmask q/k, float v)
    local_k<<<dim3(64, 8), 256>>>(qbD, kbD, spk + 2 * TBC, pre2 + TBC, lscale);

    // depthwise temporal conv on V
    dwconv_k<<<8000, 256>>>(spk + 2 * TBC, wdw, pre2 + 2 * TBC);

    // LIF over [g_pre, l_pre, dw_pre]
    lif_k<0, 0, 0><<<96, 128>>>(pre2, nullptr, nullptr, nullptr, nullptr, nullptr, nullptr,
                                spk2, nullptr, nullptr, nullptr, nullptr, nullptr, 3 * LANES);

    // pointwise over heads on dw spikes
    pw_k<<<1000, 256>>>(spk2 + 2 * TBC, wpw, dwout);

    // y0 = LIF(g + l + dw), also emit bf16 A'' for mattn GEMM
    lif_k<2, 1, 0><<<32, 128>>>(spk2, spk2 + TBC, dwout, nullptr, nullptr, nullptr, nullptr,
                                spk, As, nullptr, nullptr, nullptr, nullptr, LANES);

    // mattn GEMM + BN + LIF -> y1 (emits A'' for proj GEMM)
    wmma_gemm<<<dim3(4, 32), 256>>>(As, Bs0, pre, RR, 1536, (size_t)TBC);
    bn_part<<<dim3(16, 25, 1), 256>>>(pre, bnpart);
    bn_fin<<<1, 512>>>(bnpart, meanb, rstdb);
    lif_k<1, 1, 0><<<32, 128>>>(pre, nullptr, nullptr, meanb, rstdb,
                                gamma + 3 * 512, beta + 3 * 512, spk + TBC, As,
                                nullptr, nullptr, nullptr, nullptr, LANES);

    // proj GEMM + BN + LIF -> out
    wmma_gemm<<<dim3(4, 32), 256>>>(As, Bs1, pre, RR, 1536, (size_t)TBC);
    bn_part<<<dim3(16, 25, 1), 256>>>(pre, bnpart);
    bn_fin<<<1, 512>>>(bnpart, meanb, rstdb);
    lif_k<1, 0, 0><<<32, 128>>>(pre, nullptr, nullptr, meanb, rstdb,
                                gamma + 4 * 512, beta + 4 * 512, out, nullptr,
                                nullptr, nullptr, nullptr, nullptr, LANES);
}

// round 12
// speedup vs baseline: 1.1079x; 1.1079x over previous
#include <cuda_runtime.h>
#include <cuda_bf16.h>
#include <mma.h>
#include <math.h>
#include <stdint.h>

using namespace nvcuda;

#define TT   500
#define BB   8
#define CC   512
#define RR   4000
#define TBC  2048000
#define LANES 4096

// ---------------- scratch ----------------
__device__ float d_pre[3 * TBC];
__device__ float d_spk[3 * TBC];
__device__ float d_pre2[3 * TBC];
__device__ float d_spk2[3 * TBC];
__device__ float d_dwout[TBC];
__device__ float d_M[64 * 64 * 64];
__device__ float d_meanb[1536];
__device__ float d_rstdb[1536];
__device__ float d_bnpart[3 * 25 * 1024];
__device__ __nv_bfloat16 d_Aq[(size_t)4000 * 3072];
__device__ __nv_bfloat16 d_Bq[(size_t)1536 * 3072];
__device__ __nv_bfloat16 d_As[(size_t)4000 * 1536];
__device__ __nv_bfloat16 d_Bs0[(size_t)512 * 1536];
__device__ __nv_bfloat16 d_Bs1[(size_t)512 * 1536];
__device__ uint32_t d_qbD[65536];            // q bits along d: ((t*8+b)*8+h)*2+half
__device__ uint32_t d_kbD[65536];            // k bits along d
__device__ unsigned long long d_kbT[32768];  // k bits along t: (bh*64+d)*8+w
__device__ unsigned long long d_vbT[32768];  // v bits along t

static __device__ __forceinline__ uint32_t smem_u32(const void* p) {
    return (uint32_t)__cvta_generic_to_shared(p);
}

// ---------------- bf16 3-way split ----------------
static __device__ __forceinline__ void split3(float x, __nv_bfloat16& a,
                                              __nv_bfloat16& b, __nv_bfloat16& c) {
    a = __float2bfloat16(x);
    float r = x - __bfloat162float(a);
    b = __float2bfloat16(r);
    r = r - __bfloat162float(b);
    c = __float2bfloat16(r);
}

// A' segs = [x1, x1, x2, x1, x2, x3]
__global__ void split_x_k(const float* __restrict__ x, __nv_bfloat16* __restrict__ A)
{
    int i = blockIdx.x * 256 + threadIdx.x;
    if (i >= TBC) return;
    __nv_bfloat16 a, b, c;
    split3(x[i], a, b, c);
    size_t base = (size_t)(i >> 9) * 3072 + (i & 511);
    A[base] = a; A[base + 512] = a; A[base + 1024] = b;
    A[base + 1536] = a; A[base + 2048] = b; A[base + 2560] = c;
}

// B' segs = [w1, w2, w1, w3, w2, w1]
__global__ void split_wqkv_k(const float* __restrict__ wq, const float* __restrict__ wk,
                             const float* __restrict__ wv, __nv_bfloat16* __restrict__ B)
{
    int i = blockIdx.x * 256 + threadIdx.x;
    if (i >= 1536 * 512) return;
    int n = i >> 9, k = i & 511;
    const float* w = (n < 512) ? wq : (n < 1024) ? wk : wv;
    __nv_bfloat16 a, b, c;
    split3(w[(size_t)(n & 511) * 512 + k], a, b, c);
    size_t base = (size_t)n * 3072 + k;
    B[base] = a; B[base + 512] = b; B[base + 1024] = a;
    B[base + 1536] = c; B[base + 2048] = b; B[base + 2560] = a;
}

// B'' segs = [w1, w2, w3]
__global__ void split_ws_k(const float* __restrict__ w, __nv_bfloat16* __restrict__ B)
{
    int i = blockIdx.x * 256 + threadIdx.x;
    if (i >= 512 * 512) return;
    int n = i >> 9, k = i & 511;
    __nv_bfloat16 a, b, c;
    split3(w[(size_t)n * 512 + k], a, b, c);
    size_t base = (size_t)n * 1536 + k;
    B[base] = a; B[base + 512] = b; B[base + 1024] = c;
}

// ---------------- cp.async helper ----------------
static __device__ __forceinline__ void cpa16(uint32_t dst, const void* src, bool ok)
{
    int sz = ok ? 16 : 0;
    asm volatile("cp.async.cg.shared.global [%0], [%1], 16, %2;"
                 :: "r"(dst), "l"(src), "r"(sz));
}

// ---------------- wmma bf16 GEMM (HMMA path) — exact R9 structure ----------
#define LDT 40
#define ABYTES 10240
__global__ __launch_bounds__(256)
void wmma_gemm(const __nv_bfloat16* __restrict__ A, const __nv_bfloat16* __restrict__ B,
               float* __restrict__ outp, int Mrows, int Ktot, size_t segStride)
{
    __shared__ __align__(16) __nv_bfloat16 sm[20480];
    int tid = threadIdx.x, wid = tid >> 5, lane = tid & 31;
    int wr = wid >> 1, wc = wid & 1;
    uint32_t sa = smem_u32(sm);
    int bm = blockIdx.y * 128, bn = blockIdx.x * 128;
    const __nv_bfloat16* Ab = A + (size_t)bm * Ktot;
    const __nv_bfloat16* Bb = B + (size_t)bn * Ktot;
    int amax = Mrows - bm; if (amax > 128) amax = 128;

    int ch0 = tid, ch1 = tid + 256;
    int r0 = ch0 >> 2, c0 = (ch0 & 3) * 8;
    int r1 = ch1 >> 2, c1 = (ch1 & 3) * 8;
    int r0c = (r0 < amax) ? r0 : (amax - 1);
    int r1c = (r1 < amax) ? r1 : (amax - 1);

    int nk = Ktot >> 5;

    cpa16(sa + (uint32_t)(r0 * LDT + c0) * 2, Ab + (size_t)r0c * Ktot + c0, r0 < amax);
    cpa16(sa + (uint32_t)(r1 * LDT + c1) * 2, Ab + (size_t)r1c * Ktot + c1, r1 < amax);
    cpa16(sa + 2 * ABYTES + (uint32_t)(r0 * LDT + c0) * 2, Bb + (size_t)r0 * Ktot + c0, true);
    cpa16(sa + 2 * ABYTES + (uint32_t)(r1 * LDT + c1) * 2, Bb + (size_t)r1 * Ktot + c1, true);
    asm volatile("cp.async.commit_group;");

    wmma::fragment<wmma::accumulator, 16, 16, 16, float> acc[2][4];
#pragma unroll
    for (int i = 0; i < 2; i++)
#pragma unroll
        for (int j = 0; j < 4; j++) wmma::fill_fragment(acc[i][j], 0.0f);

    for (int k0 = 0; k0 < nk; k0++) {
        if (k0 + 1 < nk) {
            int nb = (k0 + 1) & 1;
            int kof = (k0 + 1) * 32;
            uint32_t abo = sa + (uint32_t)nb * ABYTES;
            uint32_t bbo = sa + 2 * ABYTES + (uint32_t)nb * ABYTES;
            cpa16(abo + (uint32_t)(r0 * LDT + c0) * 2, Ab + (size_t)r0c * Ktot + kof + c0, r0 < amax);
            cpa16(abo + (uint32_t)(r1 * LDT + c1) * 2, Ab + (size_t)r1c * Ktot + kof + c1, r1 < amax);
            cpa16(bbo + (uint32_t)(r0 * LDT + c0) * 2, Bb + (size_t)r0 * Ktot + kof + c0, true);
            cpa16(bbo + (uint32_t)(r1 * LDT + c1) * 2, Bb + (size_t)r1 * Ktot + kof + c1, true);
            asm volatile("cp.async.commit_group;");
            asm volatile("cp.async.wait_group 1;");
        } else {
            asm volatile("cp.async.wait_group 0;");
        }
        __syncthreads();
        int buf = k0 & 1;
        const __nv_bfloat16* As_ = sm + buf * (ABYTES / 2);
        const __nv_bfloat16* Bs_ = sm + ABYTES + buf * (ABYTES / 2);
#pragma unroll
        for (int kk = 0; kk < 2; kk++) {
            wmma::fragment<wmma::matrix_a, 16, 16, 16, __nv_bfloat16, wmma::row_major> af[2];
            wmma::fragment<wmma::matrix_b, 16, 16, 16, __nv_bfloat16, wmma::col_major> bf[4];
#pragma unroll
            for (int i = 0; i < 2; i++)
                wmma::load_matrix_sync(af[i], As_ + (wr * 32 + i * 16) * LDT + kk * 16, LDT);
#pragma unroll
            for (int j = 0; j < 4; j++)
                wmma::load_matrix_sync(bf[j], Bs_ + (wc * 64 + j * 16) * LDT + kk * 16, LDT);
#pragma unroll
            for (int i = 0; i < 2; i++)
#pragma unroll
                for (int j = 0; j < 4; j++)
                    wmma::mma_sync(acc[i][j], af[i], bf[j], acc[i][j]);
        }
        __syncthreads();
    }

    float* outbase = outp + (size_t)(bn >> 9) * segStride + (bn & 511);
    if (amax == 128) {
#pragma unroll
        for (int i = 0; i < 2; i++)
#pragma unroll
            for (int j = 0; j < 4; j++) {
                int m = bm + wr * 32 + i * 16;
                int n = wc * 64 + j * 16;
                wmma::store_matrix_sync(outbase + (size_t)m * 512 + n, acc[i][j], 512,
                                        wmma::mem_row_major);
            }
    } else {
        __syncthreads();
        float* scr = (float*)sm + wid * 256;
#pragma unroll
        for (int i = 0; i < 2; i++)
#pragma unroll
            for (int j = 0; j < 4; j++) {
                wmma::store_matrix_sync(scr, acc[i][j], 16, wmma::mem_row_major);
                __syncwarp();
#pragma unroll
                for (int q = 0; q < 8; q++) {
                    int e = lane * 8 + q;
                    int r = e >> 4, cc2 = e & 15;
                    int m = bm + wr * 32 + i * 16 + r;
                    if (m < Mrows)
                        outbase[(size_t)m * 512 + wc * 64 + j * 16 + cc2] = scr[e];
                }
                __syncwarp();
            }
    }
}

// ---------------- BN stats: deterministic 2-stage ----------------
__global__ void bn_part(const float* __restrict__ pre, float* __restrict__ part)
{
    int z = blockIdx.z;
    int cl = threadIdx.x & 31;
    int c = blockIdx.x * 32 + cl;
    int rg = threadIdx.x >> 5;
    const float* p = pre + (size_t)z * TBC;
    int r0 = blockIdx.y * 160;
    float s = 0.f, s2 = 0.f;
#pragma unroll 5
    for (int r = r0 + rg; r < r0 + 160; r += 8) {
        float v = p[(size_t)r * CC + c];
        s += v; s2 = fmaf(v, v, s2);
    }
    __shared__ float sh1[8][32], sh2[8][32];
    sh1[rg][cl] = s; sh2[rg][cl] = s2;
    __syncthreads();
    if (rg == 0) {
#pragma unroll
        for (int i = 1; i < 8; i++) { s += sh1[i][cl]; s2 += sh2[i][cl]; }
        size_t b = ((size_t)z * 25 + blockIdx.y) * 1024;
        part[b + c] = s;
        part[b + 512 + c] = s2;
    }
}

__global__ void bn_fin(const float* __restrict__ part, float* __restrict__ mean,
                       float* __restrict__ rstd)
{
    int z = blockIdx.x, c = threadIdx.x;
    float s = 0.f, s2 = 0.f;
#pragma unroll 5
    for (int i = 0; i < 25; i++) {
        size_t b = ((size_t)z * 25 + i) * 1024;
        s += part[b + c];
        s2 += part[b + 512 + c];
    }
    float m = s * (1.f / RR);
    float var = s2 * (1.f / RR) - m * m;
    mean[z * 512 + c] = m;
    rstd[z * 512 + c] = 1.f / sqrtf(var + 1e-5f);
}

// ---------------- LIF scan (exact R9 version) ----------------
// MODE 0: plain  MODE 1: BN affine  MODE 2: x = pre + a1 + a2
// WA: emit bf16 triple [s,s,s] into abuf (K=1536 layout)
template <int MODE, int WA>
__global__ void lif_k(const float* __restrict__ pre,
                      const float* __restrict__ a1, const float* __restrict__ a2,
                      const float* __restrict__ mean, const float* __restrict__ rstd,
                      const float* __restrict__ gamma, const float* __restrict__ beta,
                      float* __restrict__ out, __nv_bfloat16* __restrict__ abuf,
                      int nlanes)
{
    int lane = blockIdx.x * blockDim.x + threadIdx.x;
    if (lane >= nlanes) return;
    int m   = lane >> 12;
    int l12 = lane & 4095;
    const float* p = pre + (size_t)m * TBC + l12;
    float* o = out + (size_t)m * TBC + l12;
    float mn = 0.f, rs = 1.f, ga = 1.f, be = 0.f;
    if (MODE == 1) {
        int c = (m << 9) | (l12 & 511);
        mn = mean[c]; rs = rstd[c]; ga = gamma[c]; be = beta[c];
    }
    int bidx = l12 >> 9, cch = l12 & 511;
    float v = 0.f;
#pragma unroll 10
    for (int t = 0; t < TT; t++) {
        float x = p[(size_t)t * LANES];
        if (MODE == 2) x = x + a1[l12 + (size_t)t * LANES] + a2[l12 + (size_t)t * LANES];
        if (MODE == 1) x = ((x - mn) * rs) * ga + be;
        float h = fmaf(v, 0.5f, x);
        bool sp = (h - 1.0f) >= 0.0f;
        o[(size_t)t * LANES] = sp ? 1.0f : 0.0f;
        if (WA) {
            __nv_bfloat16 sv = __float2bfloat16(sp ? 1.0f : 0.0f);
            size_t ab = ((size_t)(t * BB + bidx)) * 1536 + cch;
            abuf[ab] = sv; abuf[ab + 512] = sv; abuf[ab + 1024] = sv;
        }
        v = sp ? 0.0f : h;
    }
}

// ---------------- spike bit-packing (standalone, after QKV LIF) ----------------
// d-direction ballots for q and k: one warp per (t*8+b, h)
__global__ void packD_k(const float* __restrict__ qspk, const float* __restrict__ kspk,
                        uint32_t* __restrict__ qbD, uint32_t* __restrict__ kbD)
{
    int tb = blockIdx.x;                       // t*8 + b
    int wid = threadIdx.x >> 5, lane = threadIdx.x & 31;
    size_t base = (size_t)tb * CC + wid * 64;
    float q0 = qspk[base + lane], q1 = qspk[base + 32 + lane];
    float k0 = kspk[base + lane], k1 = kspk[base + 32 + lane];
    unsigned mq0 = __ballot_sync(0xffffffffu, q0 > 0.5f);
    unsigned mq1 = __ballot_sync(0xffffffffu, q1 > 0.5f);
    unsigned mk0 = __ballot_sync(0xffffffffu, k0 > 0.5f);
    unsigned mk1 = __ballot_sync(0xffffffffu, k1 > 0.5f);
    if (lane == 0) {
        int ix = (tb * 8 + wid) * 2;
        qbD[ix] = mq0; qbD[ix + 1] = mq1;
        kbD[ix] = mk0; kbD[ix + 1] = mk1;
    }
}

// t-direction words for k and v: thread = (word w 0..7, lane b*512+c)
__global__ void packT_k(const float* __restrict__ kspk, const float* __restrict__ vspk,
                        unsigned long long* __restrict__ kbT,
                        unsigned long long* __restrict__ vbT)
{
    int g = blockIdx.x * 256 + threadIdx.x;    // 32768
    int w = g >> 12, l = g & 4095;
    int b = l >> 9, c = l & 511, h = c >> 6, d = c & 63;
    int bh = b * 8 + h;
    unsigned long long ck = 0, cv = 0;
    int t0 = w * 64;
    int t1 = t0 + 64; if (t1 > TT) t1 = TT;
#pragma unroll 16
    for (int t = t0; t < t1; t++) {
        size_t idx = (size_t)t * LANES + l;
        ck |= (unsigned long long)(kspk[idx] > 0.5f) << (t - t0);
        cv |= (unsigned long long)(vspk[idx] > 0.5f) << (t - t0);
    }
    kbT[(bh * 64 + d) * 8 + w] = ck;
    vbT[(bh * 64 + d) * 8 + w] = cv;
}

// ---------------- K^T V via popcount over t-packed bits ----------------
__global__ void kv_pop(const unsigned long long* __restrict__ kbT,
                       const unsigned long long* __restrict__ vbT,
                       float* __restrict__ M)
{
    __shared__ unsigned long long kb[64][8], vb[64][8];
    int bh = blockIdx.x, tid = threadIdx.x;
    for (int i = tid; i < 512; i += 256) {
        kb[i >> 3][i & 7] = kbT[bh * 512 + i];
        vb[i >> 3][i & 7] = vbT[bh * 512 + i];
    }
    __syncthreads();
#pragma unroll
    for (int q = 0; q < 16; q++) {
        int e = tid * 16 + q;
        int d1 = e >> 6, d2 = e & 63;
        int acc = 0;
#pragma unroll
        for (int w = 0; w < 8; w++) acc += __popcll(kb[d1][w] & vb[d2][w]);
        M[bh * 4096 + e] = (float)acc;
    }
}

// ---------------- global branch: g_pre = (Q M) * gscale ----------------
__global__ void qM_k(const float* __restrict__ qspk, const float* __restrict__ M,
                     float* __restrict__ gpre, float gscale)
{
    int bh = blockIdx.x; int b = bh >> 3, h = bh & 7;
    __shared__ float Ms[64][65];
    for (int i = threadIdx.x; i < 4096; i += 256) Ms[i >> 6][i & 63] = M[bh * 4096 + i];
    __syncthreads();
    int warp = threadIdx.x >> 5, lane = threadIdx.x & 31;
    int tstart = blockIdx.y * 100;
    for (int t = tstart + warp; t < tstart + 100; t += 8) {
        size_t base = (size_t)(t * BB + b) * CC + h * 64;
        float q0 = qspk[base + lane], q1 = qspk[base + 32 + lane];
        float a0 = 0.f, a1v = 0.f;
#pragma unroll
        for (int d1 = 0; d1 < 32; d1++) {
            float qv = __shfl_sync(0xffffffffu, q0, d1);
            a0 = fmaf(qv, Ms[d1][lane], a0);
            a1v = fmaf(qv, Ms[d1][lane + 32], a1v);
        }
#pragma unroll
        for (int d1 = 0; d1 < 32; d1++) {
            float qv = __shfl_sync(0xffffffffu, q1, d1);
            a0 = fmaf(qv, Ms[d1 + 32][lane], a0);
            a1v = fmaf(qv, Ms[d1 + 32][lane + 32], a1v);
        }
        gpre[base + lane] = a0 * gscale;
        gpre[base + 32 + lane] = a1v * gscale;
    }
}

// ---------------- local banded attention (bitmask q/k, float v) ----------------
__global__ void local_k(const uint32_t* __restrict__ qbD, const uint32_t* __restrict__ kbD,
                        const float* __restrict__ vspk, float* __restrict__ lpre, float lscale)
{
    int bh = blockIdx.x; int b = bh >> 3, h = bh & 7;
    int t0 = blockIdx.y * 64;
    __shared__ unsigned long long qb[64], kb[104];
    __shared__ float vsm[104][64];
    __shared__ float ss[64][41];
    int tid = threadIdx.x;
    for (int i = tid; i < 64; i += 256) {
        int t = t0 + i;
        unsigned long long w = 0;
        if (t < TT) {
            int ix = ((t * 8 + b) * 8 + h) * 2;
            w = (unsigned long long)qbD[ix] | ((unsigned long long)qbD[ix + 1] << 32);
        }
        qb[i] = w;
    }
    for (int i = tid; i < 104; i += 256) {
        int t = t0 + i - 20;
        unsigned long long w = 0;
        if (t >= 0 && t < TT) {
            int ix = ((t * 8 + b) * 8 + h) * 2;
            w = (unsigned long long)kbD[ix] | ((unsigned long long)kbD[ix + 1] << 32);
        }
        kb[i] = w;
    }
    for (int i = tid; i < 104 * 64; i += 256) {
        int r = i >> 6, dd = i & 63;
        int t = t0 + r - 20;
        vsm[r][dd] = (t >= 0 && t < TT)
                   ? vspk[(size_t)(t * BB + b) * CC + h * 64 + dd] : 0.f;
    }
    __syncthreads();
    for (int i = tid; i < 64 * 41; i += 256) {
        int tt = i / 41, o = i % 41;
        ss[tt][o] = (float)__popcll(qb[tt] & kb[tt + o]);
    }
    __syncthreads();
    int d = tid & 63, tg = tid >> 6;
    for (int tt = tg; tt < 64; tt += 4) {
        int t = t0 + tt;
        if (t >= TT) continue;
        float acc = 0.f;
#pragma unroll
        for (int o = 0; o < 41; o++) acc = fmaf(ss[tt][o], vsm[tt + o][d], acc);
        lpre[(size_t)(t * BB + b) * CC + h * 64 + d] = acc * lscale;
    }
}

// ---------------- depthwise temporal conv from packed v bits ----------------
// Identical arithmetic: acc += wdw[h*9+j] when spike bit set, in j order.
__global__ void dwconv_bits(const unsigned long long* __restrict__ vbT,
                            const float* __restrict__ wdw, float* __restrict__ out)
{
    int g = blockIdx.x * 256 + threadIdx.x;   // 32768
    int w = g >> 12, l = g & 4095;
    int b = l >> 9, c = l & 511, h = c >> 6, d = c & 63;
    int bh = b * 8 + h;
    const unsigned long long* vw = vbT + (size_t)(bh * 64 + d) * 8;
    unsigned long long w0 = (w > 0) ? vw[w - 1] : 0ull;
    unsigned long long w1 = vw[w];
    unsigned long long w2 = (w < 7) ? vw[w + 1] : 0ull;
    float wt[9];
#pragma unroll
    for (int j = 0; j < 9; j++) wt[j] = wdw[h * 9 + j];
    int t0 = w * 64;
#pragma unroll 4
    for (int tt = 0; tt < 64; tt++) {
        int t = t0 + tt;
        if (t >= TT) break;
        float acc = 0.f;
#pragma unroll
        for (int j = 0; j < 9; j++) {
            int s = tt + j - 4;
            unsigned long long word = (s < 0) ? w0 : ((s >= 64) ? w2 : w1);
            int bp = s & 63;
            if ((word >> bp) & 1ull) acc += wt[j];
        }
        out[(size_t)t * LANES + l] = acc;
    }
}

// ---------------- pointwise over heads ----------------
__global__ void pw_k(const float* __restrict__ dwspk, const float* __restrict__ wpw,
                     float* __restrict__ out)
{
    int i = blockIdx.x * 256 + threadIdx.x;
    if (i >= 256000) return;
    int t = i / 512; int bd = i % 512; int b = bd >> 6; int d = bd & 63;
    size_t base = (size_t)t * LANES + b * 512 + d;
    float s[8];
#pragma unroll
    for (int h2 = 0; h2 < 8; h2++) s[h2] = dwspk[base + h2 * 64];
#pragma unroll
    for (int g = 0; g < 8; g++) {
        float acc = 0.f;
#pragma unroll
        for (int h2 = 0; h2 < 8; h2++) acc = fmaf(s[h2], wpw[g * 8 + h2], acc);
        out[base + g * 64] = acc;
    }
}

// ---------------- host launch ----------------
extern "C" void kernel_launch(void* const* d_in, const int* in_sizes, int n_in,
                              void* d_out, int out_size)
{
    const float* x      = (const float*)d_in[0];
    const float* wq     = (const float*)d_in[1];
    const float* wk     = (const float*)d_in[2];
    const float* wv     = (const float*)d_in[3];
    const float* wmattn = (const float*)d_in[4];
    const float* wproj  = (const float*)d_in[5];
    const float* wdw    = (const float*)d_in[6];
    const float* wpw    = (const float*)d_in[7];
    const float* gamma  = (const float*)d_in[8];
    const float* beta   = (const float*)d_in[9];
    float* out = (float*)d_out;

    float *pre, *spk, *pre2, *spk2, *dwout, *M, *meanb, *rstdb, *bnpart;
    __nv_bfloat16 *Aq, *Bq, *As, *Bs0, *Bs1;
    uint32_t *qbD, *kbD;
    unsigned long long *kbT, *vbT;
    cudaGetSymbolAddress((void**)&pre,    d_pre);
    cudaGetSymbolAddress((void**)&spk,    d_spk);
    cudaGetSymbolAddress((void**)&pre2,   d_pre2);
    cudaGetSymbolAddress((void**)&spk2,   d_spk2);
    cudaGetSymbolAddress((void**)&dwout,  d_dwout);
    cudaGetSymbolAddress((void**)&M,      d_M);
    cudaGetSymbolAddress((void**)&meanb,  d_meanb);
    cudaGetSymbolAddress((void**)&rstdb,  d_rstdb);
    cudaGetSymbolAddress((void**)&bnpart, d_bnpart);
    cudaGetSymbolAddress((void**)&Aq,  d_Aq);
    cudaGetSymbolAddress((void**)&Bq,  d_Bq);
    cudaGetSymbolAddress((void**)&As,  d_As);
    cudaGetSymbolAddress((void**)&Bs0, d_Bs0);
    cudaGetSymbolAddress((void**)&Bs1, d_Bs1);
    cudaGetSymbolAddress((void**)&qbD, d_qbD);
    cudaGetSymbolAddress((void**)&kbD, d_kbD);
    cudaGetSymbolAddress((void**)&kbT, d_kbT);
    cudaGetSymbolAddress((void**)&vbT, d_vbT);

    float lscale = (float)(1.0 / (double)(float)sqrt(2624.0));
    float gscale = (float)(1.0 / (double)(float)sqrt(32000.0));

    // operand prep
    split_x_k<<<8000, 256>>>(x, Aq);
    split_wqkv_k<<<3072, 256>>>(wq, wk, wv, Bq);
    split_ws_k<<<1024, 256>>>(wmattn, Bs0);
    split_ws_k<<<1024, 256>>>(wproj, Bs1);

    // QKV: one wmma GEMM, N=1536 -> q,k,v pre-activations
    wmma_gemm<<<dim3(12, 32), 256>>>(Aq, Bq, pre, RR, 3072, (size_t)TBC);
    bn_part<<<dim3(16, 25, 3), 256>>>(pre, bnpart);
    bn_fin<<<3, 512>>>(bnpart, meanb, rstdb);
    lif_k<1, 0><<<48, 256>>>(pre, nullptr, nullptr, meanb, rstdb, gamma, beta,
                             spk, nullptr, 3 * LANES);

    // bit-pack spikes (standalone; exact)
    packD_k<<<4000, 256>>>(spk, spk + TBC, qbD, kbD);
    packT_k<<<128, 256>>>(spk + TBC, spk + 2 * TBC, kbT, vbT);

    // global linear attention: M = K^T V (popcount), then Q M
    kv_pop<<<64, 256>>>(kbT, vbT, M);
    qM_k<<<dim3(64, 5), 256>>>(spk, M, pre2, gscale);

    // local banded attention (bitmask q/k, float v)
    local_k<<<dim3(64, 8), 256>>>(qbD, kbD, spk + 2 * TBC, pre2 + TBC, lscale);

    // depthwise temporal conv on V from packed bits
    dwconv_bits<<<128, 256>>>(vbT, wdw, pre2 + 2 * TBC);

    // LIF over [g_pre, l_pre, dw_pre]
    lif_k<0, 0><<<48, 256>>>(pre2, nullptr, nullptr, nullptr, nullptr, nullptr, nullptr,
                             spk2, nullptr, 3 * LANES);

    // pointwise over heads on dw spikes
    pw_k<<<1000, 256>>>(spk2 + 2 * TBC, wpw, dwout);

    // y0 = LIF(g + l + dw), also emit bf16 A'' for mattn GEMM
    lif_k<2, 1><<<16, 256>>>(spk2, spk2 + TBC, dwout, nullptr, nullptr, nullptr, nullptr,
                             spk, As, LANES);

    // mattn GEMM + BN + LIF -> y1 (emits A'' for proj GEMM)
    wmma_gemm<<<dim3(4, 32), 256>>>(As, Bs0, pre, RR, 1536, (size_t)TBC);
    bn_part<<<dim3(16, 25, 1), 256>>>(pre, bnpart);
    bn_fin<<<1, 512>>>(bnpart, meanb, rstdb);
    lif_k<1, 1><<<16, 256>>>(pre, nullptr, nullptr, meanb, rstdb,
                             gamma + 3 * 512, beta + 3 * 512, spk + TBC, As, LANES);

    // proj GEMM + BN + LIF -> out
    wmma_gemm<<<dim3(4, 32), 256>>>(As, Bs1, pre, RR, 1536, (size_t)TBC);
    bn_part<<<dim3(16, 25, 1), 256>>>(pre, bnpart);
    bn_fin<<<1, 512>>>(bnpart, meanb, rstdb);
    lif_k<1, 0><<<16, 256>>>(pre, nullptr, nullptr, meanb, rstdb,
                             gamma + 4 * 512, beta + 4 * 512, out, nullptr, LANES);
}

// round 13
// speedup vs baseline: 1.5103x; 1.3633x over previous
#include <cuda_runtime.h>
#include <cuda_fp16.h>
#include <cuda_bf16.h>
#include <mma.h>
#include <math.h>
#include <stdint.h>

using namespace nvcuda;

#define TT   500
#define BB   8
#define CC   512
#define RR   4000
#define TBC  2048000
#define LANES 4096

// ---------------- scratch ----------------
__device__ float d_pre[3 * TBC];
__device__ float d_spk[3 * TBC];
__device__ float d_pre2[3 * TBC];
__device__ float d_spk2[3 * TBC];
__device__ float d_dwout[TBC];
__device__ float d_M[64 * 64 * 64];
__device__ float d_meanb[1536];
__device__ float d_rstdb[1536];
__device__ float d_bnpart[3 * 25 * 1024];
__device__ __half d_Aq[(size_t)4000 * 1536];
__device__ __half d_Bq[(size_t)1536 * 1536];
__device__ __half d_As[(size_t)4000 * 1024];
__device__ __half d_Bs0[(size_t)512 * 1024];
__device__ __half d_Bs1[(size_t)512 * 1024];
__device__ uint32_t d_qbD[65536];            // q bits along d: ((t*8+b)*8+h)*2+half
__device__ uint32_t d_kbD[65536];            // k bits along d
__device__ unsigned long long d_kbT[32768];  // k bits along t: (bh*64+d)*8+w
__device__ unsigned long long d_vbT[32768];  // v bits along t

static __device__ __forceinline__ uint32_t smem_u32(const void* p) {
    return (uint32_t)__cvta_generic_to_shared(p);
}

// ---------------- fp16 2-way split ----------------
static __device__ __forceinline__ void split2h(float x, __half& a, __half& b) {
    a = __float2half(x);
    b = __float2half(x - __half2float(a));
}

// A' segs = [x1, x1, x2]  (K=1536)
__global__ void split_x_k(const float* __restrict__ x, __half* __restrict__ A)
{
    int i = blockIdx.x * 256 + threadIdx.x;
    if (i >= TBC) return;
    __half a, b;
    split2h(x[i], a, b);
    size_t base = (size_t)(i >> 9) * 1536 + (i & 511);
    A[base] = a; A[base + 512] = a; A[base + 1024] = b;
}

// B' segs = [w1, w2, w1] of 256*w  (pairs: x1w1 + x1w2 + x2w1)
__global__ void split_wqkv_k(const float* __restrict__ wq, const float* __restrict__ wk,
                             const float* __restrict__ wv, __half* __restrict__ B)
{
    int i = blockIdx.x * 256 + threadIdx.x;
    if (i >= 1536 * 512) return;
    int n = i >> 9, k = i & 511;
    const float* w = (n < 512) ? wq : (n < 1024) ? wk : wv;
    __half a, b;
    split2h(256.0f * w[(size_t)(n & 511) * 512 + k], a, b);
    size_t base = (size_t)n * 1536 + k;
    B[base] = a; B[base + 512] = b; B[base + 1024] = a;
}

// B'' segs = [w1, w2] of 256*w  (K=1024; A side = [s, s])
__global__ void split_ws_k(const float* __restrict__ w, __half* __restrict__ B)
{
    int i = blockIdx.x * 256 + threadIdx.x;
    if (i >= 512 * 512) return;
    int n = i >> 9, k = i & 511;
    __half a, b;
    split2h(256.0f * w[(size_t)n * 512 + k], a, b);
    size_t base = (size_t)n * 1024 + k;
    B[base] = a; B[base + 512] = b;
}

// ---------------- cp.async helper ----------------
static __device__ __forceinline__ void cpa16(uint32_t dst, const void* src, bool ok)
{
    int sz = ok ? 16 : 0;
    asm volatile("cp.async.cg.shared.global [%0], [%1], 16, %2;"
                 :: "r"(dst), "l"(src), "r"(sz));
}

// ---------------- wmma fp16 GEMM (HMMA path) ----------
// C[m,n] = outscale * sum_k A[m,k]*B[n,k]
#define LDT 40
#define ABYTES 10240
__global__ __launch_bounds__(256)
void wmma_gemm(const __half* __restrict__ A, const __half* __restrict__ B,
               float* __restrict__ outp, int Mrows, int Ktot, size_t segStride,
               float outscale)
{
    __shared__ __align__(16) __half sm[20480];
    int tid = threadIdx.x, wid = tid >> 5, lane = tid & 31;
    int wr = wid >> 1, wc = wid & 1;
    uint32_t sa = smem_u32(sm);
    int bm = blockIdx.y * 128, bn = blockIdx.x * 128;
    const __half* Ab = A + (size_t)bm * Ktot;
    const __half* Bb = B + (size_t)bn * Ktot;
    int amax = Mrows - bm; if (amax > 128) amax = 128;

    int ch0 = tid, ch1 = tid + 256;
    int r0 = ch0 >> 2, c0 = (ch0 & 3) * 8;
    int r1 = ch1 >> 2, c1 = (ch1 & 3) * 8;
    int r0c = (r0 < amax) ? r0 : (amax - 1);
    int r1c = (r1 < amax) ? r1 : (amax - 1);

    int nk = Ktot >> 5;

    cpa16(sa + (uint32_t)(r0 * LDT + c0) * 2, Ab + (size_t)r0c * Ktot + c0, r0 < amax);
    cpa16(sa + (uint32_t)(r1 * LDT + c1) * 2, Ab + (size_t)r1c * Ktot + c1, r1 < amax);
    cpa16(sa + 2 * ABYTES + (uint32_t)(r0 * LDT + c0) * 2, Bb + (size_t)r0 * Ktot + c0, true);
    cpa16(sa + 2 * ABYTES + (uint32_t)(r1 * LDT + c1) * 2, Bb + (size_t)r1 * Ktot + c1, true);
    asm volatile("cp.async.commit_group;");

    wmma::fragment<wmma::accumulator, 16, 16, 16, float> acc[2][4];
#pragma unroll
    for (int i = 0; i < 2; i++)
#pragma unroll
        for (int j = 0; j < 4; j++) wmma::fill_fragment(acc[i][j], 0.0f);

    for (int k0 = 0; k0 < nk; k0++) {
        if (k0 + 1 < nk) {
            int nb = (k0 + 1) & 1;
            int kof = (k0 + 1) * 32;
            uint32_t abo = sa + (uint32_t)nb * ABYTES;
            uint32_t bbo = sa + 2 * ABYTES + (uint32_t)nb * ABYTES;
            cpa16(abo + (uint32_t)(r0 * LDT + c0) * 2, Ab + (size_t)r0c * Ktot + kof + c0, r0 < amax);
            cpa16(abo + (uint32_t)(r1 * LDT + c1) * 2, Ab + (size_t)r1c * Ktot + kof + c1, r1 < amax);
            cpa16(bbo + (uint32_t)(r0 * LDT + c0) * 2, Bb + (size_t)r0 * Ktot + kof + c0, true);
            cpa16(bbo + (uint32_t)(r1 * LDT + c1) * 2, Bb + (size_t)r1 * Ktot + kof + c1, true);
            asm volatile("cp.async.commit_group;");
            asm volatile("cp.async.wait_group 1;");
        } else {
            asm volatile("cp.async.wait_group 0;");
        }
        __syncthreads();
        int buf = k0 & 1;
        const __half* As_ = sm + buf * (ABYTES / 2);
        const __half* Bs_ = sm + ABYTES + buf * (ABYTES / 2);
#pragma unroll
        for (int kk = 0; kk < 2; kk++) {
            wmma::fragment<wmma::matrix_a, 16, 16, 16, __half, wmma::row_major> af[2];
            wmma::fragment<wmma::matrix_b, 16, 16, 16, __half, wmma::col_major> bf[4];
#pragma unroll
            for (int i = 0; i < 2; i++)
                wmma::load_matrix_sync(af[i], As_ + (wr * 32 + i * 16) * LDT + kk * 16, LDT);
#pragma unroll
            for (int j = 0; j < 4; j++)
                wmma::load_matrix_sync(bf[j], Bs_ + (wc * 64 + j * 16) * LDT + kk * 16, LDT);
#pragma unroll
            for (int i = 0; i < 2; i++)
#pragma unroll
                for (int j = 0; j < 4; j++)
                    wmma::mma_sync(acc[i][j], af[i], bf[j], acc[i][j]);
        }
        __syncthreads();
    }

    // exact power-of-2 rescale (undo the x256 weight pre-scale)
#pragma unroll
    for (int i = 0; i < 2; i++)
#pragma unroll
        for (int j = 0; j < 4; j++)
#pragma unroll
            for (int e = 0; e < acc[i][j].num_elements; e++)
                acc[i][j].x[e] *= outscale;

    float* outbase = outp + (size_t)(bn >> 9) * segStride + (bn & 511);
    if (amax == 128) {
#pragma unroll
        for (int i = 0; i < 2; i++)
#pragma unroll
            for (int j = 0; j < 4; j++) {
                int m = bm + wr * 32 + i * 16;
                int n = wc * 64 + j * 16;
                wmma::store_matrix_sync(outbase + (size_t)m * 512 + n, acc[i][j], 512,
                                        wmma::mem_row_major);
            }
    } else {
        __syncthreads();
        float* scr = (float*)sm + wid * 256;
#pragma unroll
        for (int i = 0; i < 2; i++)
#pragma unroll
            for (int j = 0; j < 4; j++) {
                wmma::store_matrix_sync(scr, acc[i][j], 16, wmma::mem_row_major);
                __syncwarp();
#pragma unroll
                for (int q = 0; q < 8; q++) {
                    int e = lane * 8 + q;
                    int r = e >> 4, cc2 = e & 15;
                    int m = bm + wr * 32 + i * 16 + r;
                    if (m < Mrows)
                        outbase[(size_t)m * 512 + wc * 64 + j * 16 + cc2] = scr[e];
                }
                __syncwarp();
            }
    }
}

// ---------------- BN stats: deterministic 2-stage ----------------
__global__ void bn_part(const float* __restrict__ pre, float* __restrict__ part)
{
    int z = blockIdx.z;
    int cl = threadIdx.x & 31;
    int c = blockIdx.x * 32 + cl;
    int rg = threadIdx.x >> 5;
    const float* p = pre + (size_t)z * TBC;
    int r0 = blockIdx.y * 160;
    float s = 0.f, s2 = 0.f;
#pragma unroll 5
    for (int r = r0 + rg; r < r0 + 160; r += 8) {
        float v = p[(size_t)r * CC + c];
        s += v; s2 = fmaf(v, v, s2);
    }
    __shared__ float sh1[8][32], sh2[8][32];
    sh1[rg][cl] = s; sh2[rg][cl] = s2;
    __syncthreads();
    if (rg == 0) {
#pragma unroll
        for (int i = 1; i < 8; i++) { s += sh1[i][cl]; s2 += sh2[i][cl]; }
        size_t b = ((size_t)z * 25 + blockIdx.y) * 1024;
        part[b + c] = s;
        part[b + 512 + c] = s2;
    }
}

__global__ void bn_fin(const float* __restrict__ part, float* __restrict__ mean,
                       float* __restrict__ rstd)
{
    int z = blockIdx.x, c = threadIdx.x;
    float s = 0.f, s2 = 0.f;
#pragma unroll 5
    for (int i = 0; i < 25; i++) {
        size_t b = ((size_t)z * 25 + i) * 1024;
        s += part[b + c];
        s2 += part[b + 512 + c];
    }
    float m = s * (1.f / RR);
    float var = s2 * (1.f / RR) - m * m;
    mean[z * 512 + c] = m;
    rstd[z * 512 + c] = 1.f / sqrtf(var + 1e-5f);
}

// ---------------- LIF scan ----------------
// MODE 0: plain  MODE 1: BN affine  MODE 2: x = pre + a1 + a2
// WA: emit fp16 pair [s,s] into abuf (K=1024 layout)
template <int MODE, int WA>
__global__ void lif_k(const float* __restrict__ pre,
                      const float* __restrict__ a1, const float* __restrict__ a2,
                      const float* __restrict__ mean, const float* __restrict__ rstd,
                      const float* __restrict__ gamma, const float* __restrict__ beta,
                      float* __restrict__ out, __half* __restrict__ abuf,
                      int nlanes)
{
    int lane = blockIdx.x * blockDim.x + threadIdx.x;
    if (lane >= nlanes) return;
    int m   = lane >> 12;
    int l12 = lane & 4095;
    const float* p = pre + (size_t)m * TBC + l12;
    float* o = out + (size_t)m * TBC + l12;
    float mn = 0.f, rs = 1.f, ga = 1.f, be = 0.f;
    if (MODE == 1) {
        int c = (m << 9) | (l12 & 511);
        mn = mean[c]; rs = rstd[c]; ga = gamma[c]; be = beta[c];
    }
    int bidx = l12 >> 9, cch = l12 & 511;
    float v = 0.f;
#pragma unroll 20
    for (int t = 0; t < TT; t++) {
        float x = p[(size_t)t * LANES];
        if (MODE == 2) x = x + a1[l12 + (size_t)t * LANES] + a2[l12 + (size_t)t * LANES];
        if (MODE == 1) x = ((x - mn) * rs) * ga + be;
        float h = fmaf(v, 0.5f, x);
        bool sp = (h - 1.0f) >= 0.0f;
        o[(size_t)t * LANES] = sp ? 1.0f : 0.0f;
        if (WA) {
            __half sv = __float2half(sp ? 1.0f : 0.0f);
            size_t ab = ((size_t)(t * BB + bidx)) * 1024 + cch;
            abuf[ab] = sv; abuf[ab + 512] = sv;
        }
        v = sp ? 0.0f : h;
    }
}

// ---------------- spike bit-packing ----------------
__global__ void packD_k(const float* __restrict__ qspk, const float* __restrict__ kspk,
                        uint32_t* __restrict__ qbD, uint32_t* __restrict__ kbD)
{
    int tb = blockIdx.x;                       // t*8 + b
    int wid = threadIdx.x >> 5, lane = threadIdx.x & 31;
    size_t base = (size_t)tb * CC + wid * 64;
    float q0 = qspk[base + lane], q1 = qspk[base + 32 + lane];
    float k0 = kspk[base + lane], k1 = kspk[base + 32 + lane];
    unsigned mq0 = __ballot_sync(0xffffffffu, q0 > 0.5f);
    unsigned mq1 = __ballot_sync(0xffffffffu, q1 > 0.5f);
    unsigned mk0 = __ballot_sync(0xffffffffu, k0 > 0.5f);
    unsigned mk1 = __ballot_sync(0xffffffffu, k1 > 0.5f);
    if (lane == 0) {
        int ix = (tb * 8 + wid) * 2;
        qbD[ix] = mq0; qbD[ix + 1] = mq1;
        kbD[ix] = mk0; kbD[ix + 1] = mk1;
    }
}

__global__ void packT_k(const float* __restrict__ kspk, const float* __restrict__ vspk,
                        unsigned long long* __restrict__ kbT,
                        unsigned long long* __restrict__ vbT)
{
    int g = blockIdx.x * 256 + threadIdx.x;    // 32768
    int w = g >> 12, l = g & 4095;
    int b = l >> 9, c = l & 511, h = c >> 6, d = c & 63;
    int bh = b * 8 + h;
    unsigned long long ck = 0, cv = 0;
    int t0 = w * 64;
    int t1 = t0 + 64; if (t1 > TT) t1 = TT;
#pragma unroll 16
    for (int t = t0; t < t1; t++) {
        size_t idx = (size_t)t * LANES + l;
        ck |= (unsigned long long)(kspk[idx] > 0.5f) << (t - t0);
        cv |= (unsigned long long)(vspk[idx] > 0.5f) << (t - t0);
    }
    kbT[(bh * 64 + d) * 8 + w] = ck;
    vbT[(bh * 64 + d) * 8 + w] = cv;
}

// ---------------- K^T V via popcount ----------------
__global__ void kv_pop(const unsigned long long* __restrict__ kbT,
                       const unsigned long long* __restrict__ vbT,
                       float* __restrict__ M)
{
    __shared__ unsigned long long kb[64][8], vb[64][8];
    int bh = blockIdx.x, tid = threadIdx.x;
    for (int i = tid; i < 512; i += 256) {
        kb[i >> 3][i & 7] = kbT[bh * 512 + i];
        vb[i >> 3][i & 7] = vbT[bh * 512 + i];
    }
    __syncthreads();
#pragma unroll
    for (int q = 0; q < 16; q++) {
        int e = tid * 16 + q;
        int d1 = e >> 6, d2 = e & 63;
        int acc = 0;
#pragma unroll
        for (int w = 0; w < 8; w++) acc += __popcll(kb[d1][w] & vb[d2][w]);
        M[bh * 4096 + e] = (float)acc;
    }
}

// ---------------- global branch: g_pre = (Q M) * gscale ----------------
__global__ void qM_k(const float* __restrict__ qspk, const float* __restrict__ M,
                     float* __restrict__ gpre, float gscale)
{
    int bh = blockIdx.x; int b = bh >> 3, h = bh & 7;
    __shared__ float Ms[64][65];
    for (int i = threadIdx.x; i < 4096; i += 256) Ms[i >> 6][i & 63] = M[bh * 4096 + i];
    __syncthreads();
    int warp = threadIdx.x >> 5, lane = threadIdx.x & 31;
    int tstart = blockIdx.y * 100;
    for (int t = tstart + warp; t < tstart + 100; t += 8) {
        size_t base = (size_t)(t * BB + b) * CC + h * 64;
        float q0 = qspk[base + lane], q1 = qspk[base + 32 + lane];
        float a0 = 0.f, a1v = 0.f;
#pragma unroll
        for (int d1 = 0; d1 < 32; d1++) {
            float qv = __shfl_sync(0xffffffffu, q0, d1);
            a0 = fmaf(qv, Ms[d1][lane], a0);
            a1v = fmaf(qv, Ms[d1][lane + 32], a1v);
        }
#pragma unroll
        for (int d1 = 0; d1 < 32; d1++) {
            float qv = __shfl_sync(0xffffffffu, q1, d1);
            a0 = fmaf(qv, Ms[d1 + 32][lane], a0);
            a1v = fmaf(qv, Ms[d1 + 32][lane + 32], a1v);
        }
        gpre[base + lane] = a0 * gscale;
        gpre[base + 32 + lane] = a1v * gscale;
    }
}

// ---------------- local banded attention ----------------
__global__ void local_k(const uint32_t* __restrict__ qbD, const uint32_t* __restrict__ kbD,
                        const float* __restrict__ vspk, float* __restrict__ lpre, float lscale)
{
    int bh = blockIdx.x; int b = bh >> 3, h = bh & 7;
    int t0 = blockIdx.y * 64;
    __shared__ unsigned long long qb[64], kb[104];
    __shared__ float vsm[104][64];
    __shared__ float ss[64][41];
    int tid = threadIdx.x;
    for (int i = tid; i < 64; i += 256) {
        int t = t0 + i;
        unsigned long long w = 0;
        if (t < TT) {
            int ix = ((t * 8 + b) * 8 + h) * 2;
            w = (unsigned long long)qbD[ix] | ((unsigned long long)qbD[ix + 1] << 32);
        }
        qb[i] = w;
    }
    for (int i = tid; i < 104; i += 256) {
        int t = t0 + i - 20;
        unsigned long long w = 0;
        if (t >= 0 && t < TT) {
            int ix = ((t * 8 + b) * 8 + h) * 2;
            w = (unsigned long long)kbD[ix] | ((unsigned long long)kbD[ix + 1] << 32);
        }
        kb[i] = w;
    }
    for (int i = tid; i < 104 * 64; i += 256) {
        int r = i >> 6, dd = i & 63;
        int t = t0 + r - 20;
        vsm[r][dd] = (t >= 0 && t < TT)
                   ? vspk[(size_t)(t * BB + b) * CC + h * 64 + dd] : 0.f;
    }
    __syncthreads();
    for (int i = tid; i < 64 * 41; i += 256) {
        int tt = i / 41, o = i % 41;
        ss[tt][o] = (float)__popcll(qb[tt] & kb[tt + o]);
    }
    __syncthreads();
    int d = tid & 63, tg = tid >> 6;
    for (int tt = tg; tt < 64; tt += 4) {
        int t = t0 + tt;
        if (t >= TT) continue;
        float acc = 0.f;
#pragma unroll
        for (int o = 0; o < 41; o++) acc = fmaf(ss[tt][o], vsm[tt + o][d], acc);
        lpre[(size_t)(t * BB + b) * CC + h * 64 + d] = acc * lscale;
    }
}

// ---------------- depthwise temporal conv from packed v bits ----------------
__global__ void dwconv_bits(const unsigned long long* __restrict__ vbT,
                            const float* __restrict__ wdw, float* __restrict__ out)
{
    int g = blockIdx.x * 256 + threadIdx.x;   // 32768
    int w = g >> 12, l = g & 4095;
    int b = l >> 9, c = l & 511, h = c >> 6, d = c & 63;
    int bh = b * 8 + h;
    const unsigned long long* vw = vbT + (size_t)(bh * 64 + d) * 8;
    unsigned long long w0 = (w > 0) ? vw[w - 1] : 0ull;
    unsigned long long w1 = vw[w];
    unsigned long long w2 = (w < 7) ? vw[w + 1] : 0ull;
    float wt[9];
#pragma unroll
    for (int j = 0; j < 9; j++) wt[j] = wdw[h * 9 + j];
    int t0 = w * 64;
#pragma unroll 4
    for (int tt = 0; tt < 64; tt++) {
        int t = t0 + tt;
        if (t >= TT) break;
        float acc = 0.f;
#pragma unroll
        for (int j = 0; j < 9; j++) {
            int s = tt + j - 4;
            unsigned long long word = (s < 0) ? w0 : ((s >= 64) ? w2 : w1);
            int bp = s & 63;
            if ((word >> bp) & 1ull) acc += wt[j];
        }
        out[(size_t)t * LANES + l] = acc;
    }
}

// ---------------- pointwise over heads ----------------
__global__ void pw_k(const float* __restrict__ dwspk, const float* __restrict__ wpw,
                     float* __restrict__ out)
{
    int i = blockIdx.x * 256 + threadIdx.x;
    if (i >= 256000) return;
    int t = i / 512; int bd = i % 512; int b = bd >> 6; int d = bd & 63;
    size_t base = (size_t)t * LANES + b * 512 + d;
    float s[8];
#pragma unroll
    for (int h2 = 0; h2 < 8; h2++) s[h2] = dwspk[base + h2 * 64];
#pragma unroll
    for (int g = 0; g < 8; g++) {
        float acc = 0.f;
#pragma unroll
        for (int h2 = 0; h2 < 8; h2++) acc = fmaf(s[h2], wpw[g * 8 + h2], acc);
        out[base + g * 64] = acc;
    }
}

// ---------------- host launch ----------------
extern "C" void kernel_launch(void* const* d_in, const int* in_sizes, int n_in,
                              void* d_out, int out_size)
{
    const float* x      = (const float*)d_in[0];
    const float* wq     = (const float*)d_in[1];
    const float* wk     = (const float*)d_in[2];
    const float* wv     = (const float*)d_in[3];
    const float* wmattn = (const float*)d_in[4];
    const float* wproj  = (const float*)d_in[5];
    const float* wdw    = (const float*)d_in[6];
    const float* wpw    = (const float*)d_in[7];
    const float* gamma  = (const float*)d_in[8];
    const float* beta   = (const float*)d_in[9];
    float* out = (float*)d_out;

    float *pre, *spk, *pre2, *spk2, *dwout, *M, *meanb, *rstdb, *bnpart;
    __half *Aq, *Bq, *As, *Bs0, *Bs1;
    uint32_t *qbD, *kbD;
    unsigned long long *kbT, *vbT;
    cudaGetSymbolAddress((void**)&pre,    d_pre);
    cudaGetSymbolAddress((void**)&spk,    d_spk);
    cudaGetSymbolAddress((void**)&pre2,   d_pre2);
    cudaGetSymbolAddress((void**)&spk2,   d_spk2);
    cudaGetSymbolAddress((void**)&dwout,  d_dwout);
    cudaGetSymbolAddress((void**)&M,      d_M);
    cudaGetSymbolAddress((void**)&meanb,  d_meanb);
    cudaGetSymbolAddress((void**)&rstdb,  d_rstdb);
    cudaGetSymbolAddress((void**)&bnpart, d_bnpart);
    cudaGetSymbolAddress((void**)&Aq,  d_Aq);
    cudaGetSymbolAddress((void**)&Bq,  d_Bq);
    cudaGetSymbolAddress((void**)&As,  d_As);
    cudaGetSymbolAddress((void**)&Bs0, d_Bs0);
    cudaGetSymbolAddress((void**)&Bs1, d_Bs1);
    cudaGetSymbolAddress((void**)&qbD, d_qbD);
    cudaGetSymbolAddress((void**)&kbD, d_kbD);
    cudaGetSymbolAddress((void**)&kbT, d_kbT);
    cudaGetSymbolAddress((void**)&vbT, d_vbT);

    float lscale = (float)(1.0 / (double)(float)sqrt(2624.0));
    float gscale = (float)(1.0 / (double)(float)sqrt(32000.0));
    const float inv256 = 1.0f / 256.0f;

    // operand prep (fp16 2-way splits; weights pre-scaled by 256)
    split_x_k<<<8000, 256>>>(x, Aq);
    split_wqkv_k<<<3072, 256>>>(wq, wk, wv, Bq);
    split_ws_k<<<1024, 256>>>(wmattn, Bs0);
    split_ws_k<<<1024, 256>>>(wproj, Bs1);

    // QKV: one fp16 GEMM, K=1536, N=1536
    wmma_gemm<<<dim3(12, 32), 256>>>(Aq, Bq, pre, RR, 1536, (size_t)TBC, inv256);
    bn_part<<<dim3(16, 25, 3), 256>>>(pre, bnpart);
    bn_fin<<<3, 512>>>(bnpart, meanb, rstdb);
    lif_k<1, 0><<<48, 256>>>(pre, nullptr, nullptr, meanb, rstdb, gamma, beta,
                             spk, nullptr, 3 * LANES);

    // bit-pack spikes
    packD_k<<<4000, 256>>>(spk, spk + TBC, qbD, kbD);
    packT_k<<<128, 256>>>(spk + TBC, spk + 2 * TBC, kbT, vbT);

    // global linear attention: M = K^T V (popcount), then Q M
    kv_pop<<<64, 256>>>(kbT, vbT, M);
    qM_k<<<dim3(64, 5), 256>>>(spk, M, pre2, gscale);

    // local banded attention
    local_k<<<dim3(64, 8), 256>>>(qbD, kbD, spk + 2 * TBC, pre2 + TBC, lscale);

    // depthwise temporal conv from packed bits
    dwconv_bits<<<128, 256>>>(vbT, wdw, pre2 + 2 * TBC);

    // LIF over [g_pre, l_pre, dw_pre]
    lif_k<0, 0><<<48, 256>>>(pre2, nullptr, nullptr, nullptr, nullptr, nullptr, nullptr,
                             spk2, nullptr, 3 * LANES);

    // pointwise over heads on dw spikes
    pw_k<<<1000, 256>>>(spk2 + 2 * TBC, wpw, dwout);

    // y0 = LIF(g + l + dw), emits fp16 A'' for mattn GEMM
    lif_k<2, 1><<<16, 256>>>(spk2, spk2 + TBC, dwout, nullptr, nullptr, nullptr, nullptr,
                             spk, As, LANES);

    // mattn GEMM (K=1024) + BN + LIF -> y1 (emits A'' for proj GEMM)
    wmma_gemm<<<dim3(4, 32), 256>>>(As, Bs0, pre, RR, 1024, (size_t)TBC, inv256);
    bn_part<<<dim3(16, 25, 1), 256>>>(pre, bnpart);
    bn_fin<<<1, 512>>>(bnpart, meanb, rstdb);
    lif_k<1, 1><<<16, 256>>>(pre, nullptr, nullptr, meanb, rstdb,
                             gamma + 3 * 512, beta + 3 * 512, spk + TBC, As, LANES);

    // proj GEMM (K=1024) + BN + LIF -> out
    wmma_gemm<<<dim3(4, 32), 256>>>(As, Bs1, pre, RR, 1024, (size_t)TBC, inv256);
    bn_part<<<dim3(16, 25, 1), 256>>>(pre, bnpart);
    bn_fin<<<1, 512>>>(bnpart, meanb, rstdb);
    lif_k<1, 0><<<16, 256>>>(pre, nullptr, nullptr, meanb, rstdb,
                             gamma + 4 * 512, beta + 4 * 512, out, nullptr, LANES);
}